// round 1
// baseline (speedup 1.0000x reference)
#include <cuda_runtime.h>

// CausalAttentionProduct — flash-attention, SIMT fp32 baseline.
// B=2, H=12, S=4096, D=64. Output fp32.
//
// Reference quirk: scores[..., -128:, -128:] is OVERWRITTEN with
// (0 if k<=q else finfo.min) before softmax (mask not added there).

#define NB 2
#define NH 12
#define S_LEN 4096
#define DH 64
#define BM 64
#define BN 64
#define SPECIAL_LO (S_LEN - 128)
#define LOG2E 1.4426950408889634f
#define NEG_BIG (-1e30f)

// dynamic smem layout (floats):
//   Qt [64][64]  k-major, offset 0      (4096)
//   Kt [64][65]  k-major, offset 4096   (4160)
//   Pt [64][65]  k-major, offset 8256   (4160)
//   Vs [64][68]  k-rows,  offset 12416  (4352)
//   mk [64]               offset 16768  (64)
#define OFF_QT 0
#define OFF_KT 4096
#define OFF_PT 8256
#define OFF_VS 12416
#define OFF_MK 16768
#define SMEM_FLOATS 16832
#define SMEM_BYTES (SMEM_FLOATS * 4)

extern __shared__ float smem[];

__global__ void __launch_bounds__(128, 3)
attn_fwd_kernel(const float* __restrict__ Q,
                const float* __restrict__ K,
                const float* __restrict__ V,
                const float* __restrict__ mask,
                float* __restrict__ O)
{
    float* Qt = smem + OFF_QT;
    float* Kt = smem + OFF_KT;
    float* Pt = smem + OFF_PT;
    float* Vs = smem + OFF_VS;
    float* mk = smem + OFF_MK;

    const int tid = threadIdx.x;
    const int tx = tid & 7;     // 0..7  (cols: n/d = tx + 8c)
    const int ty = tid >> 3;    // 0..15 (rows: m = ty + 16r)
    const int bh = blockIdx.y;
    const int b  = bh / NH;
    const int qbase = blockIdx.x * BM;

    const float* Qp = Q + (size_t)bh * S_LEN * DH;
    const float* Kp = K + (size_t)bh * S_LEN * DH;
    const float* Vp = V + (size_t)bh * S_LEN * DH;
    const float* Mp = mask + (size_t)b * S_LEN;
    float* Op = O + (size_t)bh * S_LEN * DH;

    // ---- load Q tile, transposed to k-major, with softmax scale folded in ----
    const float qscale = 0.125f * LOG2E;   // 1/sqrt(64) * log2(e)
    {
        const int row = tid >> 4;          // 0..7
        const int c4  = tid & 15;          // 0..15 (float4 index along D)
        #pragma unroll
        for (int rr = 0; rr < 8; rr++) {
            int m = row + rr * 8;
            float4 v = *(const float4*)(Qp + (size_t)(qbase + m) * DH + c4 * 4);
            Qt[(c4*4+0)*64 + m] = v.x * qscale;
            Qt[(c4*4+1)*64 + m] = v.y * qscale;
            Qt[(c4*4+2)*64 + m] = v.z * qscale;
            Qt[(c4*4+3)*64 + m] = v.w * qscale;
        }
    }

    float m_r[4], l_r[4], acc[4][8];
    #pragma unroll
    for (int r = 0; r < 4; r++) {
        m_r[r] = NEG_BIG;
        l_r[r] = 0.0f;
        #pragma unroll
        for (int c = 0; c < 8; c++) acc[r][c] = 0.0f;
    }

    const bool q_special = (qbase >= SPECIAL_LO);

    for (int kt = 0; kt < S_LEN / BN; kt++) {
        const int kbase = kt * BN;

        __syncthreads();  // previous iter's smem consumers done

        // ---- load K (transposed to k-major) + V (as-is) + mask column chunk ----
        {
            const int row = tid >> 4;
            const int c4  = tid & 15;
            #pragma unroll
            for (int rr = 0; rr < 8; rr++) {
                int n = row + rr * 8;
                float4 kv = *(const float4*)(Kp + (size_t)(kbase + n) * DH + c4 * 4);
                Kt[(c4*4+0)*65 + n] = kv.x;
                Kt[(c4*4+1)*65 + n] = kv.y;
                Kt[(c4*4+2)*65 + n] = kv.z;
                Kt[(c4*4+3)*65 + n] = kv.w;
                float4 vv = *(const float4*)(Vp + (size_t)(kbase + n) * DH + c4 * 4);
                *(float4*)(Vs + n * 68 + c4 * 4) = vv;
            }
            if (tid < 64) mk[tid] = Mp[kbase + tid] * LOG2E;
        }
        __syncthreads();

        // ---- S = (scaled Q) @ K^T ----
        float s[4][8];
        #pragma unroll
        for (int r = 0; r < 4; r++)
            #pragma unroll
            for (int c = 0; c < 8; c++) s[r][c] = 0.0f;

        #pragma unroll 4
        for (int kk = 0; kk < DH; kk++) {
            float a[4], bb[8];
            #pragma unroll
            for (int r = 0; r < 4; r++) a[r] = Qt[kk*64 + ty + 16*r];
            #pragma unroll
            for (int c = 0; c < 8; c++) bb[c] = Kt[kk*65 + tx + 8*c];
            #pragma unroll
            for (int r = 0; r < 4; r++)
                #pragma unroll
                for (int c = 0; c < 8; c++)
                    s[r][c] = fmaf(a[r], bb[c], s[r][c]);
        }

        // ---- mask / special bottom-right block (overwrite semantics) ----
        if (q_special && (kbase >= SPECIAL_LO)) {
            #pragma unroll
            for (int r = 0; r < 4; r++) {
                int qg = qbase + ty + 16*r;
                #pragma unroll
                for (int c = 0; c < 8; c++) {
                    int ng = kbase + tx + 8*c;
                    s[r][c] = (ng <= qg) ? 0.0f : NEG_BIG;
                }
            }
        } else {
            #pragma unroll
            for (int c = 0; c < 8; c++) {
                float mv = mk[tx + 8*c];
                #pragma unroll
                for (int r = 0; r < 4; r++) s[r][c] += mv;
            }
        }

        // ---- online softmax (exp2 domain) ----
        #pragma unroll
        for (int r = 0; r < 4; r++) {
            float tm = s[r][0];
            #pragma unroll
            for (int c = 1; c < 8; c++) tm = fmaxf(tm, s[r][c]);
            tm = fmaxf(tm, __shfl_xor_sync(0xffffffffu, tm, 1));
            tm = fmaxf(tm, __shfl_xor_sync(0xffffffffu, tm, 2));
            tm = fmaxf(tm, __shfl_xor_sync(0xffffffffu, tm, 4));
            float mn = fmaxf(m_r[r], tm);
            float sc = exp2f(m_r[r] - mn);
            m_r[r] = mn;
            float ls = 0.0f;
            #pragma unroll
            for (int c = 0; c < 8; c++) {
                float p = exp2f(s[r][c] - mn);
                s[r][c] = p;
                ls += p;
            }
            ls += __shfl_xor_sync(0xffffffffu, ls, 1);
            ls += __shfl_xor_sync(0xffffffffu, ls, 2);
            ls += __shfl_xor_sync(0xffffffffu, ls, 4);
            l_r[r] = l_r[r] * sc + ls;
            #pragma unroll
            for (int c = 0; c < 8; c++) acc[r][c] *= sc;
        }

        // ---- store P transposed to k-major: Pt[n][m] ----
        #pragma unroll
        for (int c = 0; c < 8; c++) {
            int n = tx + 8*c;
            #pragma unroll
            for (int r = 0; r < 4; r++)
                Pt[n*65 + ty + 16*r] = s[r][c];
        }
        __syncthreads();

        // ---- O += P @ V ----
        #pragma unroll 4
        for (int kk = 0; kk < BN; kk++) {
            float a[4], bb[8];
            #pragma unroll
            for (int r = 0; r < 4; r++) a[r] = Pt[kk*65 + ty + 16*r];
            #pragma unroll
            for (int c = 0; c < 8; c++) bb[c] = Vs[kk*68 + tx + 8*c];
            #pragma unroll
            for (int r = 0; r < 4; r++)
                #pragma unroll
                for (int c = 0; c < 8; c++)
                    acc[r][c] = fmaf(a[r], bb[c], acc[r][c]);
        }
    }

    // ---- epilogue: normalize and write ----
    #pragma unroll
    for (int r = 0; r < 4; r++) {
        float inv = 1.0f / l_r[r];
        size_t m = (size_t)(qbase + ty + 16*r);
        #pragma unroll
        for (int c = 0; c < 8; c++)
            Op[m * DH + tx + 8*c] = acc[r][c] * inv;
    }
}

extern "C" void kernel_launch(void* const* d_in, const int* in_sizes, int n_in,
                              void* d_out, int out_size)
{
    (void)in_sizes; (void)n_in; (void)out_size;
    const float* Q    = (const float*)d_in[0];
    const float* K    = (const float*)d_in[1];
    const float* V    = (const float*)d_in[2];
    const float* mask = (const float*)d_in[3];
    float* O = (float*)d_out;

    cudaFuncSetAttribute(attn_fwd_kernel,
                         cudaFuncAttributeMaxDynamicSharedMemorySize, SMEM_BYTES);

    dim3 grid(S_LEN / BM, NB * NH);
    attn_fwd_kernel<<<grid, 128, SMEM_BYTES>>>(Q, K, V, mask, O);
}

// round 2
// speedup vs baseline: 3.5097x; 3.5097x over previous
#include <cuda_runtime.h>
#include <cstdint>

// CausalAttentionProduct — flash attention with legacy tf32 mma.sync (HMMA).
// B=2, H=12, S=4096, D=64. fp32 in/out. BM=128, BN=64, 4 warps.
// Reference quirk: scores[..., -128:, -128:] OVERWRITTEN with (0 if k<=q else -inf).

#define NB 2
#define NH 12
#define S_LEN 4096
#define DH 64
#define BM 128
#define BN 64
#define NWARP 4
#define LOG2E 1.4426950408889634f
#define NEG_BIG (-1e30f)

// smem layout (floats). Pitches chosen for conflict-free fragment access:
//  Qs[128][68], Ks[64][68]: bank = 4g+tg (unique over warp)
//  Vs[64][72]:  bank = 8tg+g (unique over warp)
//  Ps[4][32][68]: reads unique; STS.64 writes 2-way (accepted, ~2%)
#define QS_PITCH 68
#define KS_PITCH 68
#define VS_PITCH 72
#define PS_PITCH 68
#define OFF_QS 0
#define OFF_KS (OFF_QS + BM * QS_PITCH)
#define OFF_VS (OFF_KS + BN * KS_PITCH)
#define OFF_PS (OFF_VS + BN * VS_PITCH)
#define OFF_MK (OFF_PS + NWARP * 32 * PS_PITCH)
#define SMEM_FLOATS (OFF_MK + BN)
#define SMEM_BYTES (SMEM_FLOATS * 4)

extern __shared__ float smem[];

__device__ __forceinline__ uint32_t f2tf(float x) {
    uint32_t r;
    asm("cvt.rna.tf32.f32 %0, %1;" : "=r"(r) : "f"(x));
    return r;
}
__device__ __forceinline__ float ex2(float x) {
    float r;
    asm("ex2.approx.ftz.f32 %0, %1;" : "=f"(r) : "f"(x));
    return r;
}
__device__ __forceinline__ void mma_tf32(float c[4],
                                         uint32_t a0, uint32_t a1, uint32_t a2, uint32_t a3,
                                         uint32_t b0, uint32_t b1) {
    asm volatile(
        "mma.sync.aligned.m16n8k8.row.col.f32.tf32.tf32.f32 "
        "{%0,%1,%2,%3}, {%4,%5,%6,%7}, {%8,%9}, {%0,%1,%2,%3};"
        : "+f"(c[0]), "+f"(c[1]), "+f"(c[2]), "+f"(c[3])
        : "r"(a0), "r"(a1), "r"(a2), "r"(a3), "r"(b0), "r"(b1));
}

__global__ void __launch_bounds__(128)
attn_tf32_kernel(const float* __restrict__ Q,
                 const float* __restrict__ K,
                 const float* __restrict__ V,
                 const float* __restrict__ mask,
                 float* __restrict__ O)
{
    float* Qs = smem + OFF_QS;
    float* Ks = smem + OFF_KS;
    float* Vs = smem + OFF_VS;
    float* mk = smem + OFF_MK;

    const int tid  = threadIdx.x;
    const int warp = tid >> 5;
    const int lane = tid & 31;
    const int g    = lane >> 2;   // 0..7
    const int tg   = lane & 3;    // 0..3

    float* Ps = smem + OFF_PS + warp * 32 * PS_PITCH;

    const int bh    = blockIdx.y;
    const int b     = bh / NH;
    const int qbase = blockIdx.x * BM;
    const bool qsp  = (qbase == S_LEN - BM);   // last q tile holds the special rows

    const float* Qp = Q + (size_t)bh * S_LEN * DH;
    const float* Kp = K + (size_t)bh * S_LEN * DH;
    const float* Vp = V + (size_t)bh * S_LEN * DH;
    const float* Mp = mask + (size_t)b * S_LEN;
    float* Op = O + (size_t)bh * S_LEN * DH;

    // ---- load Q tile (scale 1/sqrt(d)*log2e folded in) ----
    {
        const float qscale = 0.125f * LOG2E;
        const int r0 = tid >> 4;      // 0..7
        const int c4 = tid & 15;      // float4 col
        #pragma unroll
        for (int i = 0; i < 16; i++) {
            int m = r0 + 8 * i;
            float4 v = *(const float4*)(Qp + (size_t)(qbase + m) * DH + c4 * 4);
            v.x *= qscale; v.y *= qscale; v.z *= qscale; v.w *= qscale;
            *(float4*)(Qs + m * QS_PITCH + c4 * 4) = v;
        }
    }

    // per-thread state: 4 row-slots = (at in 0..1) x (rh in 0..1)
    float m_st[2][2], l_st[2][2];
    float oacc[2][8][4];
    #pragma unroll
    for (int at = 0; at < 2; at++)
        #pragma unroll
        for (int rh = 0; rh < 2; rh++) { m_st[at][rh] = NEG_BIG; l_st[at][rh] = 0.0f; }
    #pragma unroll
    for (int at = 0; at < 2; at++)
        #pragma unroll
        for (int nt = 0; nt < 8; nt++)
            #pragma unroll
            for (int j = 0; j < 4; j++) oacc[at][nt][j] = 0.0f;

    const int wrow = warp * 32;   // warp's first q row within tile

    for (int kt = 0; kt < S_LEN / BN; kt++) {
        const int kbase = kt * BN;

        __syncthreads();   // all warps done reading Ks/Vs of previous tile

        // ---- load K,V tiles + mask chunk ----
        {
            const int r0 = tid >> 4;
            const int c4 = tid & 15;
            #pragma unroll
            for (int i = 0; i < 8; i++) {
                int n = r0 + 8 * i;
                float4 kv = *(const float4*)(Kp + (size_t)(kbase + n) * DH + c4 * 4);
                *(float4*)(Ks + n * KS_PITCH + c4 * 4) = kv;
                float4 vv = *(const float4*)(Vp + (size_t)(kbase + n) * DH + c4 * 4);
                *(float4*)(Vs + n * VS_PITCH + c4 * 4) = vv;
            }
            if (tid < BN) mk[tid] = Mp[kbase + tid] * LOG2E;
        }
        __syncthreads();

        // ---- S = Q @ K^T  (tf32 mma) ----
        float sacc[2][8][4];
        #pragma unroll
        for (int at = 0; at < 2; at++)
            #pragma unroll
            for (int nt = 0; nt < 8; nt++)
                #pragma unroll
                for (int j = 0; j < 4; j++) sacc[at][nt][j] = 0.0f;

        #pragma unroll
        for (int ks = 0; ks < 8; ks++) {
            uint32_t a[2][4];
            #pragma unroll
            for (int at = 0; at < 2; at++) {
                const float* qr = Qs + (wrow + at * 16 + g) * QS_PITCH + ks * 8;
                a[at][0] = f2tf(qr[tg]);
                a[at][1] = f2tf(qr[8 * QS_PITCH + tg]);
                a[at][2] = f2tf(qr[tg + 4]);
                a[at][3] = f2tf(qr[8 * QS_PITCH + tg + 4]);
            }
            #pragma unroll
            for (int nt = 0; nt < 8; nt++) {
                const float* kr = Ks + (nt * 8 + g) * KS_PITCH + ks * 8;
                uint32_t b0 = f2tf(kr[tg]);
                uint32_t b1 = f2tf(kr[tg + 4]);
                mma_tf32(sacc[0][nt], a[0][0], a[0][1], a[0][2], a[0][3], b0, b1);
                mma_tf32(sacc[1][nt], a[1][0], a[1][1], a[1][2], a[1][3], b0, b1);
            }
        }

        // ---- mask add / special bottom-right overwrite ----
        if (qsp && kbase >= S_LEN - 128) {
            #pragma unroll
            for (int at = 0; at < 2; at++)
                #pragma unroll
                for (int nt = 0; nt < 8; nt++)
                    #pragma unroll
                    for (int j = 0; j < 4; j++) {
                        int qg = qbase + wrow + at * 16 + g + (j >> 1) * 8;
                        int kg = kbase + nt * 8 + 2 * tg + (j & 1);
                        sacc[at][nt][j] = (kg <= qg) ? 0.0f : NEG_BIG;
                    }
        } else {
            #pragma unroll
            for (int nt = 0; nt < 8; nt++) {
                float2 mv = *(const float2*)(mk + nt * 8 + 2 * tg);
                #pragma unroll
                for (int at = 0; at < 2; at++) {
                    sacc[at][nt][0] += mv.x;
                    sacc[at][nt][1] += mv.y;
                    sacc[at][nt][2] += mv.x;
                    sacc[at][nt][3] += mv.y;
                }
            }
        }

        // ---- online softmax (exp2 domain), per row-slot ----
        #pragma unroll
        for (int at = 0; at < 2; at++) {
            #pragma unroll
            for (int rh = 0; rh < 2; rh++) {
                float tm = NEG_BIG;
                #pragma unroll
                for (int nt = 0; nt < 8; nt++) {
                    tm = fmaxf(tm, sacc[at][nt][2 * rh]);
                    tm = fmaxf(tm, sacc[at][nt][2 * rh + 1]);
                }
                tm = fmaxf(tm, __shfl_xor_sync(0xffffffffu, tm, 1));
                tm = fmaxf(tm, __shfl_xor_sync(0xffffffffu, tm, 2));
                float mn = fmaxf(m_st[at][rh], tm);
                float corr = ex2(m_st[at][rh] - mn);
                m_st[at][rh] = mn;
                float ls = 0.0f;
                #pragma unroll
                for (int nt = 0; nt < 8; nt++) {
                    float p0 = ex2(sacc[at][nt][2 * rh] - mn);
                    float p1 = ex2(sacc[at][nt][2 * rh + 1] - mn);
                    sacc[at][nt][2 * rh] = p0;
                    sacc[at][nt][2 * rh + 1] = p1;
                    ls += p0 + p1;
                }
                ls += __shfl_xor_sync(0xffffffffu, ls, 1);
                ls += __shfl_xor_sync(0xffffffffu, ls, 2);
                l_st[at][rh] = l_st[at][rh] * corr + ls;
                #pragma unroll
                for (int nt = 0; nt < 8; nt++) {
                    oacc[at][nt][2 * rh] *= corr;
                    oacc[at][nt][2 * rh + 1] *= corr;
                }
            }
        }

        // ---- P -> smem (c-layout to a-layout conversion) ----
        __syncwarp();
        #pragma unroll
        for (int at = 0; at < 2; at++)
            #pragma unroll
            for (int nt = 0; nt < 8; nt++)
                #pragma unroll
                for (int rh = 0; rh < 2; rh++) {
                    float2 pv = make_float2(sacc[at][nt][2 * rh], sacc[at][nt][2 * rh + 1]);
                    *(float2*)(Ps + (at * 16 + g + 8 * rh) * PS_PITCH + nt * 8 + 2 * tg) = pv;
                }
        __syncwarp();

        // ---- O += P @ V  (tf32 mma) ----
        #pragma unroll
        for (int ks = 0; ks < 8; ks++) {
            uint32_t a[2][4];
            #pragma unroll
            for (int at = 0; at < 2; at++) {
                const float* pr = Ps + (at * 16 + g) * PS_PITCH + ks * 8;
                a[at][0] = f2tf(pr[tg]);
                a[at][1] = f2tf(pr[8 * PS_PITCH + tg]);
                a[at][2] = f2tf(pr[tg + 4]);
                a[at][3] = f2tf(pr[8 * PS_PITCH + tg + 4]);
            }
            #pragma unroll
            for (int nt = 0; nt < 8; nt++) {
                const float* vr = Vs + (ks * 8 + tg) * VS_PITCH + nt * 8 + g;
                uint32_t b0 = f2tf(vr[0]);
                uint32_t b1 = f2tf(vr[4 * VS_PITCH]);
                mma_tf32(oacc[0][nt], a[0][0], a[0][1], a[0][2], a[0][3], b0, b1);
                mma_tf32(oacc[1][nt], a[1][0], a[1][1], a[1][2], a[1][3], b0, b1);
            }
        }
    }

    // ---- epilogue ----
    #pragma unroll
    for (int at = 0; at < 2; at++) {
        #pragma unroll
        for (int rh = 0; rh < 2; rh++) {
            float inv = 1.0f / l_st[at][rh];
            size_t row = (size_t)(qbase + wrow + at * 16 + g + 8 * rh);
            #pragma unroll
            for (int nt = 0; nt < 8; nt++) {
                float2 ov = make_float2(oacc[at][nt][2 * rh] * inv,
                                        oacc[at][nt][2 * rh + 1] * inv);
                *(float2*)(Op + row * DH + nt * 8 + 2 * tg) = ov;
            }
        }
    }
}

extern "C" void kernel_launch(void* const* d_in, const int* in_sizes, int n_in,
                              void* d_out, int out_size)
{
    (void)in_sizes; (void)n_in; (void)out_size;
    const float* Q    = (const float*)d_in[0];
    const float* K    = (const float*)d_in[1];
    const float* V    = (const float*)d_in[2];
    const float* mask = (const float*)d_in[3];
    float* O = (float*)d_out;

    cudaFuncSetAttribute(attn_tf32_kernel,
                         cudaFuncAttributeMaxDynamicSharedMemorySize, SMEM_BYTES);

    dim3 grid(S_LEN / BM, NB * NH);
    attn_tf32_kernel<<<grid, 128, SMEM_BYTES>>>(Q, K, V, mask, O);
}